// round 1
// baseline (speedup 1.0000x reference)
#include <cuda_runtime.h>
#include <math.h>
#include <stdio.h>

#define Bz   128
#define Sz   50
#define Tz   32
#define TQz  32
#define Hz   256
#define Vz   50257
#define H3   768

// ---------------- scratch (device globals; no allocation allowed) ----------------
__device__ float g_ctx [Bz*Sz*Hz];     // position-encoded context (B,S,H)
__device__ float g_qemb[Bz*TQz*Hz];    // question embeddings (B,TQ,H)
__device__ float g_gif [Bz*Sz*H3];     // x@Wih_f^T + bih_f
__device__ float g_gib [Bz*Sz*H3];     // x@Wih_b^T + bih_b (natural s order)
__device__ float g_giq [Bz*TQz*H3];    // q@Wih_q^T + bih_q
__device__ float g_whhT[3*Hz*H3];      // transposed recurrent weights [gru][k][j]
__device__ float g_h   [3*2*Bz*Hz];    // hidden double buffers [gru][parity][b][h]
__device__ float g_outf[Bz*Sz*Hz];     // fwd outputs per s
__device__ float g_outb[Bz*Sz*Hz];     // bwd outputs stored at reversed (facts) position
__device__ float g_v   [Bz*Hz];        // tanh(q*read)

__device__ __forceinline__ float sigmoidf_(float x){ return 1.f/(1.f+expf(-x)); }

// ---------------- init ----------------
__global__ void init_h(){
    int i = blockIdx.x*blockDim.x + threadIdx.x;
    if (i < 3*2*Bz*Hz) g_h[i] = 0.f;
}

// ---------------- transpose Whh (768x256 -> 256x768) for all 3 GRUs ----------------
__global__ void transpose_whh(const float* __restrict__ Wf,
                              const float* __restrict__ Wb,
                              const float* __restrict__ Wq){
    const float* W = (blockIdx.z==0)?Wf:(blockIdx.z==1)?Wb:Wq;
    float* out = g_whhT + (size_t)blockIdx.z*Hz*H3;
    __shared__ float tile[32][33];
    int j0 = blockIdx.x*32, k0 = blockIdx.y*32;
    for (int r = threadIdx.y; r < 32; r += 8)
        tile[r][threadIdx.x] = W[(size_t)(j0+r)*Hz + k0 + threadIdx.x];
    __syncthreads();
    for (int r = threadIdx.y; r < 32; r += 8)
        out[(size_t)(k0+r)*H3 + j0 + threadIdx.x] = tile[threadIdx.x][r];
}

// ---------------- embedding + position encoding ----------------
__global__ void embed_ctx(const int* __restrict__ contexts, const float* __restrict__ emb){
    int bs = blockIdx.x;              // b*S + s
    int tid = threadIdx.x;            // h
    __shared__ int sidx[Tz];
    if (tid < Tz) sidx[tid] = contexts[(size_t)bs*Tz + tid];
    __syncthreads();
    float e = (float)tid * (1.f/(float)(Hz-1));
    float acc = 0.f;
    #pragma unroll 4
    for (int t = 0; t < Tz; t++){
        float sf = (float)t * (1.f/(float)(Tz-1));
        float l = 1.f - sf - e*(1.f - 2.f*sf);
        acc += emb[(size_t)sidx[t]*Hz + tid] * l;
    }
    g_ctx[(size_t)bs*Hz + tid] = acc;
}

__global__ void embed_q(const int* __restrict__ questions, const float* __restrict__ emb){
    int i = blockIdx.x;               // b*TQ + t
    int tok = questions[i];
    g_qemb[(size_t)i*Hz + threadIdx.x] = emb[(size_t)tok*Hz + threadIdx.x];
}

// ---------------- generic NT GEMM: C[m,n] = sum_k A[m,k]*Bw[n,k] + bias[n] ----------------
// BM=BN=128, BK=16, 256 threads, 8x8 per-thread tile
__global__ void __launch_bounds__(256) gemm_nt(const float* __restrict__ A,
                                               const float* __restrict__ Bw,
                                               const float* __restrict__ bias,
                                               float* __restrict__ C,
                                               int M, int N, int K){
    __shared__ float As[16][128];
    __shared__ float Bs[16][128];
    int bm = blockIdx.y*128, bn = blockIdx.x*128;
    int tid = threadIdx.x;
    int tr = tid >> 4, tc = tid & 15;
    float acc[8][8];
    #pragma unroll
    for (int i=0;i<8;i++)
        #pragma unroll
        for (int j=0;j<8;j++) acc[i][j] = 0.f;

    for (int k0 = 0; k0 < K; k0 += 16){
        #pragma unroll
        for (int i = 0; i < 2; i++){
            int id  = tid + i*256;     // 0..511
            int row = id >> 2;
            int kq  = (id & 3) << 2;
            float4 v = make_float4(0.f,0.f,0.f,0.f);
            int gr = bm + row;
            if (gr < M) v = *(const float4*)(A + (size_t)gr*K + k0 + kq);
            As[kq+0][row]=v.x; As[kq+1][row]=v.y; As[kq+2][row]=v.z; As[kq+3][row]=v.w;
            float4 w = make_float4(0.f,0.f,0.f,0.f);
            int gw = bn + row;
            if (gw < N) w = *(const float4*)(Bw + (size_t)gw*K + k0 + kq);
            Bs[kq+0][row]=w.x; Bs[kq+1][row]=w.y; Bs[kq+2][row]=w.z; Bs[kq+3][row]=w.w;
        }
        __syncthreads();
        #pragma unroll
        for (int k = 0; k < 16; k++){
            float a0[8], b0[8];
            *(float4*)&a0[0] = *(const float4*)&As[k][tr*8];
            *(float4*)&a0[4] = *(const float4*)&As[k][tr*8+4];
            *(float4*)&b0[0] = *(const float4*)&Bs[k][tc*8];
            *(float4*)&b0[4] = *(const float4*)&Bs[k][tc*8+4];
            #pragma unroll
            for (int i=0;i<8;i++)
                #pragma unroll
                for (int j=0;j<8;j++)
                    acc[i][j] += a0[i]*b0[j];
        }
        __syncthreads();
    }
    #pragma unroll
    for (int i=0;i<8;i++){
        int m = bm + tr*8 + i;
        if (m >= M) continue;
        #pragma unroll
        for (int j=0;j<8;j++){
            int n = bn + tc*8 + j;
            if (n < N) C[(size_t)m*N + n] = acc[i][j] + bias[n];
        }
    }
}

// ---------------- GRU step: gh = h @ Whh^T, gates, h update ----------------
// grid (4 b-tiles of 32, 16 j-tiles of 16, 3 grus), 128 threads
__global__ void __launch_bounds__(128) gru_step(int t, int cur,
                                                const float* __restrict__ bhh_f,
                                                const float* __restrict__ bhh_b,
                                                const float* __restrict__ bhh_q){
    int gru = blockIdx.z;
    if (gru == 2 && t >= TQz) return;
    int b0 = blockIdx.x * 32;
    int jb = blockIdx.y * 16;
    int tid = threadIdx.x;
    int tx = tid & 15;    // j within tile
    int ty = tid >> 4;    // 0..7, group of 4 batch rows

    __shared__ float shh[Hz][36];     // h tile transposed [k][b], padded (36KB)
    __shared__ float shw[32][48];     // WT chunk: 48 cols = {r,z,n} x 16 j

    const float* hin  = g_h + (size_t)(gru*2 + cur)*Bz*Hz;
    float*       hout = g_h + (size_t)(gru*2 + (cur^1))*Bz*Hz;

    for (int i = tid; i < 32*Hz; i += 128){
        int bb = i >> 8; int k = i & 255;
        shh[k][bb] = hin[(size_t)(b0+bb)*Hz + k];
    }
    const float* WT = g_whhT + (size_t)gru*Hz*H3;

    float ar[4] = {0,0,0,0}, az[4] = {0,0,0,0}, an[4] = {0,0,0,0};

    for (int k0 = 0; k0 < Hz; k0 += 32){
        __syncthreads();
        for (int i = tid; i < 32*48; i += 128){
            int kk = i / 48; int c = i % 48;
            int g = c >> 4; int jj = c & 15;
            shw[kk][c] = WT[(size_t)(k0+kk)*H3 + g*Hz + jb + jj];
        }
        __syncthreads();
        #pragma unroll
        for (int kk = 0; kk < 32; kk++){
            int k = k0 + kk;
            float4 hv = *(const float4*)&shh[k][ty*4];
            float wr = shw[kk][tx], wz = shw[kk][16+tx], wn = shw[kk][32+tx];
            ar[0] += hv.x*wr; ar[1] += hv.y*wr; ar[2] += hv.z*wr; ar[3] += hv.w*wr;
            az[0] += hv.x*wz; az[1] += hv.y*wz; az[2] += hv.z*wz; az[3] += hv.w*wz;
            an[0] += hv.x*wn; an[1] += hv.y*wn; an[2] += hv.z*wn; an[3] += hv.w*wn;
        }
    }

    const float* bhh = (gru==0)?bhh_f:(gru==1)?bhh_b:bhh_q;
    int j = jb + tx;
    float br = bhh[j], bz = bhh[Hz+j], bn = bhh[2*Hz+j];

    #pragma unroll
    for (int i = 0; i < 4; i++){
        int bb = ty*4 + i; int b = b0 + bb;
        const float* gi;
        if      (gru == 0) gi = g_gif + (size_t)(b*Sz + t)*H3;
        else if (gru == 1) gi = g_gib + (size_t)(b*Sz + (Sz-1-t))*H3;
        else               gi = g_giq + (size_t)(b*TQz + t)*H3;
        float r = sigmoidf_(gi[j]      + ar[i] + br);
        float z = sigmoidf_(gi[Hz+j]   + az[i] + bz);
        float n = tanhf   (gi[2*Hz+j]  + r*(an[i] + bn));
        float hold = shh[j][bb];
        float hnew = (1.f - z)*n + z*hold;
        hout[(size_t)b*Hz + j] = hnew;
        if      (gru == 0) g_outf[(size_t)(b*Sz + t)*Hz + j]        = hnew;
        else if (gru == 1) g_outb[(size_t)(b*Sz + (Sz-1-t))*Hz + j] = hnew;
    }
}

// ---------------- attention + read + tanh(q*read) ----------------
__global__ void attn_kernel(){
    int b = blockIdx.x, tid = threadIdx.x;
    int lane = tid & 31, wid = tid >> 5;
    __shared__ float sq[Hz];
    __shared__ float se[Sz];
    __shared__ float sa[Sz];
    sq[tid] = g_h[(size_t)(2*2 + 0)*Bz*Hz + (size_t)b*Hz + tid];  // q after 32 steps -> parity 0
    __syncthreads();
    for (int s = wid; s < Sz; s += 8){
        const float* pf = g_outf + (size_t)(b*Sz+s)*Hz;
        const float* pb = g_outb + (size_t)(b*Sz+s)*Hz;
        float p = 0.f;
        for (int h = lane; h < Hz; h += 32) p += (pf[h]+pb[h])*sq[h];
        #pragma unroll
        for (int o = 16; o > 0; o >>= 1) p += __shfl_xor_sync(0xffffffffu, p, o);
        if (lane == 0) se[s] = p;
    }
    __syncthreads();
    if (tid < 32){
        float e1 = (tid      < Sz)? se[tid]    : -1e30f;
        float e2 = (tid + 32 < Sz)? se[tid+32] : -1e30f;
        float m = fmaxf(e1, e2);
        #pragma unroll
        for (int o = 16; o > 0; o >>= 1) m = fmaxf(m, __shfl_xor_sync(0xffffffffu, m, o));
        float x1 = (tid      < Sz)? expf(e1 - m) : 0.f;
        float x2 = (tid + 32 < Sz)? expf(e2 - m) : 0.f;
        float ss = x1 + x2;
        #pragma unroll
        for (int o = 16; o > 0; o >>= 1) ss += __shfl_xor_sync(0xffffffffu, ss, o);
        float inv = 1.f/ss;
        if (tid      < Sz) sa[tid]    = x1*inv;
        if (tid + 32 < Sz) sa[tid+32] = x2*inv;
    }
    __syncthreads();
    float r = 0.f;
    for (int s = 0; s < Sz; s++)
        r += sa[s]*(g_outf[(size_t)(b*Sz+s)*Hz + tid] + g_outb[(size_t)(b*Sz+s)*Hz + tid]);
    g_v[(size_t)b*Hz + tid] = tanhf(sq[tid]*r);
}

// ---------------- launch ----------------
extern "C" void kernel_launch(void* const* d_in, const int* in_sizes, int n_in,
                              void* d_out, int out_size){
    const int*   contexts  = (const int*)  d_in[0];
    const int*   questions = (const int*)  d_in[1];
    const float* emb       = (const float*)d_in[2];
    const float* Wih_f = (const float*)d_in[3];
    const float* Whh_f = (const float*)d_in[4];
    const float* bih_f = (const float*)d_in[5];
    const float* bhh_f = (const float*)d_in[6];
    const float* Wih_b = (const float*)d_in[7];
    const float* Whh_b = (const float*)d_in[8];
    const float* bih_b = (const float*)d_in[9];
    const float* bhh_b = (const float*)d_in[10];
    const float* Wih_q = (const float*)d_in[11];
    const float* Whh_q = (const float*)d_in[12];
    const float* bih_q = (const float*)d_in[13];
    const float* bhh_q = (const float*)d_in[14];
    const float* Wo    = (const float*)d_in[15];
    const float* bo    = (const float*)d_in[16];
    float* out = (float*)d_out;

    // resolve device-global scratch addresses for the generic GEMM
    void *p_ctx, *p_qemb, *p_gif, *p_gib, *p_giq, *p_v;
    cudaGetSymbolAddress(&p_ctx,  g_ctx);
    cudaGetSymbolAddress(&p_qemb, g_qemb);
    cudaGetSymbolAddress(&p_gif,  g_gif);
    cudaGetSymbolAddress(&p_gib,  g_gib);
    cudaGetSymbolAddress(&p_giq,  g_giq);
    cudaGetSymbolAddress(&p_v,    g_v);

    init_h<<<(3*2*Bz*Hz + 255)/256, 256>>>();
    transpose_whh<<<dim3(H3/32, Hz/32, 3), dim3(32, 8)>>>(Whh_f, Whh_b, Whh_q);
    embed_ctx<<<Bz*Sz, Hz>>>(contexts, emb);
    embed_q  <<<Bz*TQz, Hz>>>(questions, emb);

    // gi GEMMs (bias = bih folded in)
    gemm_nt<<<dim3(H3/128, (Bz*Sz)/128),  256>>>((const float*)p_ctx,  Wih_f, bih_f, (float*)p_gif, Bz*Sz,  H3, Hz);
    gemm_nt<<<dim3(H3/128, (Bz*Sz)/128),  256>>>((const float*)p_ctx,  Wih_b, bih_b, (float*)p_gib, Bz*Sz,  H3, Hz);
    gemm_nt<<<dim3(H3/128, (Bz*TQz)/128), 256>>>((const float*)p_qemb, Wih_q, bih_q, (float*)p_giq, Bz*TQz, H3, Hz);

    // recurrence: fwd + bwd (50 steps) and question (first 32 steps), fused per step
    for (int t = 0; t < Sz; t++)
        gru_step<<<dim3(Bz/32, Hz/16, 3), 128>>>(t, t & 1, bhh_f, bhh_b, bhh_q);

    attn_kernel<<<Bz, Hz>>>();

    // out = tanh(q*read) @ Wo^T + bo : (128, 50257)
    gemm_nt<<<dim3((Vz + 127)/128, 1), 256>>>((const float*)p_v, Wo, bo, out, Bz, Vz, Hz);
}

// round 2
// speedup vs baseline: 1.0172x; 1.0172x over previous
#include <cuda_runtime.h>
#include <math.h>
#include <stdio.h>

#define Bz   128
#define Sz   50
#define Tz   32
#define TQz  32
#define Hz   256
#define Vz   50257
#define H3   768

// ---------------- scratch (device globals; no allocation allowed) ----------------
__device__ float g_ctx [Bz*Sz*Hz];     // position-encoded context (B,S,H)
__device__ float g_qemb[Bz*TQz*Hz];    // question embeddings (B,TQ,H)
__device__ float g_gif [Bz*Sz*H3];     // x@Wih_f^T + bih_f
__device__ float g_gib [Bz*Sz*H3];     // x@Wih_b^T + bih_b (natural s order)
__device__ float g_giq [Bz*TQz*H3];    // q@Wih_q^T + bih_q
__device__ float g_whhT[3*Hz*H3];      // transposed recurrent weights [gru][k][j]
__device__ float g_h   [3*2*Bz*Hz];    // hidden double buffers [gru][parity][b][h]
__device__ float g_outf[Bz*Sz*Hz];     // fwd outputs per s
__device__ float g_outb[Bz*Sz*Hz];     // bwd outputs stored at reversed (facts) position
__device__ float g_v   [Bz*Hz];        // tanh(q*read)

__device__ __forceinline__ float sigmoidf_(float x){ return 1.f/(1.f+expf(-x)); }

// ---------------- init ----------------
__global__ void init_h(){
    int i = blockIdx.x*blockDim.x + threadIdx.x;
    if (i < 3*2*Bz*Hz) g_h[i] = 0.f;
}

// ---------------- transpose Whh (768x256 -> 256x768) for all 3 GRUs ----------------
__global__ void transpose_whh(const float* __restrict__ Wf,
                              const float* __restrict__ Wb,
                              const float* __restrict__ Wq){
    const float* W = (blockIdx.z==0)?Wf:(blockIdx.z==1)?Wb:Wq;
    float* out = g_whhT + (size_t)blockIdx.z*Hz*H3;
    __shared__ float tile[32][33];
    int j0 = blockIdx.x*32, k0 = blockIdx.y*32;
    for (int r = threadIdx.y; r < 32; r += 8)
        tile[r][threadIdx.x] = W[(size_t)(j0+r)*Hz + k0 + threadIdx.x];
    __syncthreads();
    for (int r = threadIdx.y; r < 32; r += 8)
        out[(size_t)(k0+r)*H3 + j0 + threadIdx.x] = tile[threadIdx.x][r];
}

// ---------------- embedding + position encoding ----------------
__global__ void embed_ctx(const int* __restrict__ contexts, const float* __restrict__ emb){
    int bs = blockIdx.x;              // b*S + s
    int tid = threadIdx.x;            // h
    __shared__ int sidx[Tz];
    if (tid < Tz) sidx[tid] = contexts[(size_t)bs*Tz + tid];
    __syncthreads();
    float e = (float)tid * (1.f/(float)(Hz-1));
    float acc = 0.f;
    #pragma unroll 4
    for (int t = 0; t < Tz; t++){
        float sf = (float)t * (1.f/(float)(Tz-1));
        float l = 1.f - sf - e*(1.f - 2.f*sf);
        acc += emb[(size_t)sidx[t]*Hz + tid] * l;
    }
    g_ctx[(size_t)bs*Hz + tid] = acc;
}

__global__ void embed_q(const int* __restrict__ questions, const float* __restrict__ emb){
    int i = blockIdx.x;               // b*TQ + t
    int tok = questions[i];
    g_qemb[(size_t)i*Hz + threadIdx.x] = emb[(size_t)tok*Hz + threadIdx.x];
}

// ---------------- generic NT GEMM: C[m,n] = sum_k A[m,k]*Bw[n,k] + bias[n] ----------------
// BM=BN=128, BK=16, 256 threads, 8x8 per-thread tile
__global__ void __launch_bounds__(256) gemm_nt(const float* __restrict__ A,
                                               const float* __restrict__ Bw,
                                               const float* __restrict__ bias,
                                               float* __restrict__ C,
                                               int M, int N, int K){
    __shared__ float As[16][128];
    __shared__ float Bs[16][128];
    int bm = blockIdx.y*128, bn = blockIdx.x*128;
    int tid = threadIdx.x;
    int tr = tid >> 4, tc = tid & 15;
    float acc[8][8];
    #pragma unroll
    for (int i=0;i<8;i++)
        #pragma unroll
        for (int j=0;j<8;j++) acc[i][j] = 0.f;

    for (int k0 = 0; k0 < K; k0 += 16){
        #pragma unroll
        for (int i = 0; i < 2; i++){
            int id  = tid + i*256;     // 0..511
            int row = id >> 2;
            int kq  = (id & 3) << 2;
            float4 v = make_float4(0.f,0.f,0.f,0.f);
            int gr = bm + row;
            if (gr < M) v = *(const float4*)(A + (size_t)gr*K + k0 + kq);
            As[kq+0][row]=v.x; As[kq+1][row]=v.y; As[kq+2][row]=v.z; As[kq+3][row]=v.w;
            float4 w = make_float4(0.f,0.f,0.f,0.f);
            int gw = bn + row;
            if (gw < N) w = *(const float4*)(Bw + (size_t)gw*K + k0 + kq);
            Bs[kq+0][row]=w.x; Bs[kq+1][row]=w.y; Bs[kq+2][row]=w.z; Bs[kq+3][row]=w.w;
        }
        __syncthreads();
        #pragma unroll
        for (int k = 0; k < 16; k++){
            float a0[8], b0[8];
            *(float4*)&a0[0] = *(const float4*)&As[k][tr*8];
            *(float4*)&a0[4] = *(const float4*)&As[k][tr*8+4];
            *(float4*)&b0[0] = *(const float4*)&Bs[k][tc*8];
            *(float4*)&b0[4] = *(const float4*)&Bs[k][tc*8+4];
            #pragma unroll
            for (int i=0;i<8;i++)
                #pragma unroll
                for (int j=0;j<8;j++)
                    acc[i][j] += a0[i]*b0[j];
        }
        __syncthreads();
    }
    #pragma unroll
    for (int i=0;i<8;i++){
        int m = bm + tr*8 + i;
        if (m >= M) continue;
        #pragma unroll
        for (int j=0;j<8;j++){
            int n = bn + tc*8 + j;
            if (n < N) C[(size_t)m*N + n] = acc[i][j] + bias[n];
        }
    }
}

// ---------------- GRU step: gh = h @ Whh^T, gates, h update ----------------
// grid (4 b-tiles of 32, 16 j-tiles of 16, 3 grus), 128 threads
__global__ void __launch_bounds__(128) gru_step(int t, int cur,
                                                const float* __restrict__ bhh_f,
                                                const float* __restrict__ bhh_b,
                                                const float* __restrict__ bhh_q){
    int gru = blockIdx.z;
    if (gru == 2 && t >= TQz) return;
    int b0 = blockIdx.x * 32;
    int jb = blockIdx.y * 16;
    int tid = threadIdx.x;
    int tx = tid & 15;    // j within tile
    int ty = tid >> 4;    // 0..7, group of 4 batch rows

    __shared__ float shh[Hz][36];     // h tile transposed [k][b], padded (36KB)
    __shared__ float shw[32][48];     // WT chunk: 48 cols = {r,z,n} x 16 j

    const float* hin  = g_h + (size_t)(gru*2 + cur)*Bz*Hz;
    float*       hout = g_h + (size_t)(gru*2 + (cur^1))*Bz*Hz;

    for (int i = tid; i < 32*Hz; i += 128){
        int bb = i >> 8; int k = i & 255;
        shh[k][bb] = hin[(size_t)(b0+bb)*Hz + k];
    }
    const float* WT = g_whhT + (size_t)gru*Hz*H3;

    float ar[4] = {0,0,0,0}, az[4] = {0,0,0,0}, an[4] = {0,0,0,0};

    for (int k0 = 0; k0 < Hz; k0 += 32){
        __syncthreads();
        for (int i = tid; i < 32*48; i += 128){
            int kk = i / 48; int c = i % 48;
            int g = c >> 4; int jj = c & 15;
            shw[kk][c] = WT[(size_t)(k0+kk)*H3 + g*Hz + jb + jj];
        }
        __syncthreads();
        #pragma unroll
        for (int kk = 0; kk < 32; kk++){
            int k = k0 + kk;
            float4 hv = *(const float4*)&shh[k][ty*4];
            float wr = shw[kk][tx], wz = shw[kk][16+tx], wn = shw[kk][32+tx];
            ar[0] += hv.x*wr; ar[1] += hv.y*wr; ar[2] += hv.z*wr; ar[3] += hv.w*wr;
            az[0] += hv.x*wz; az[1] += hv.y*wz; az[2] += hv.z*wz; az[3] += hv.w*wz;
            an[0] += hv.x*wn; an[1] += hv.y*wn; an[2] += hv.z*wn; an[3] += hv.w*wn;
        }
    }

    const float* bhh = (gru==0)?bhh_f:(gru==1)?bhh_b:bhh_q;
    int j = jb + tx;
    float br = bhh[j], bz = bhh[Hz+j], bn = bhh[2*Hz+j];

    #pragma unroll
    for (int i = 0; i < 4; i++){
        int bb = ty*4 + i; int b = b0 + bb;
        const float* gi;
        if      (gru == 0) gi = g_gif + (size_t)(b*Sz + t)*H3;
        else if (gru == 1) gi = g_gib + (size_t)(b*Sz + (Sz-1-t))*H3;
        else               gi = g_giq + (size_t)(b*TQz + t)*H3;
        float r = sigmoidf_(gi[j]      + ar[i] + br);
        float z = sigmoidf_(gi[Hz+j]   + az[i] + bz);
        float n = tanhf   (gi[2*Hz+j]  + r*(an[i] + bn));
        float hold = shh[j][bb];
        float hnew = (1.f - z)*n + z*hold;
        hout[(size_t)b*Hz + j] = hnew;
        if      (gru == 0) g_outf[(size_t)(b*Sz + t)*Hz + j]        = hnew;
        else if (gru == 1) g_outb[(size_t)(b*Sz + (Sz-1-t))*Hz + j] = hnew;
    }
}

// ---------------- attention + read + tanh(q*read) ----------------
__global__ void attn_kernel(){
    int b = blockIdx.x, tid = threadIdx.x;
    int lane = tid & 31, wid = tid >> 5;
    __shared__ float sq[Hz];
    __shared__ float se[Sz];
    __shared__ float sa[Sz];
    sq[tid] = g_h[(size_t)(2*2 + 0)*Bz*Hz + (size_t)b*Hz + tid];  // q after 32 steps -> parity 0
    __syncthreads();
    for (int s = wid; s < Sz; s += 8){
        const float* pf = g_outf + (size_t)(b*Sz+s)*Hz;
        const float* pb = g_outb + (size_t)(b*Sz+s)*Hz;
        float p = 0.f;
        for (int h = lane; h < Hz; h += 32) p += (pf[h]+pb[h])*sq[h];
        #pragma unroll
        for (int o = 16; o > 0; o >>= 1) p += __shfl_xor_sync(0xffffffffu, p, o);
        if (lane == 0) se[s] = p;
    }
    __syncthreads();
    if (tid < 32){
        float e1 = (tid      < Sz)? se[tid]    : -1e30f;
        float e2 = (tid + 32 < Sz)? se[tid+32] : -1e30f;
        float m = fmaxf(e1, e2);
        #pragma unroll
        for (int o = 16; o > 0; o >>= 1) m = fmaxf(m, __shfl_xor_sync(0xffffffffu, m, o));
        float x1 = (tid      < Sz)? expf(e1 - m) : 0.f;
        float x2 = (tid + 32 < Sz)? expf(e2 - m) : 0.f;
        float ss = x1 + x2;
        #pragma unroll
        for (int o = 16; o > 0; o >>= 1) ss += __shfl_xor_sync(0xffffffffu, ss, o);
        float inv = 1.f/ss;
        if (tid      < Sz) sa[tid]    = x1*inv;
        if (tid + 32 < Sz) sa[tid+32] = x2*inv;
    }
    __syncthreads();
    float r = 0.f;
    for (int s = 0; s < Sz; s++)
        r += sa[s]*(g_outf[(size_t)(b*Sz+s)*Hz + tid] + g_outb[(size_t)(b*Sz+s)*Hz + tid]);
    g_v[(size_t)b*Hz + tid] = tanhf(sq[tid]*r);
}

// ---------------- launch ----------------
extern "C" void kernel_launch(void* const* d_in, const int* in_sizes, int n_in,
                              void* d_out, int out_size){
    const int*   contexts  = (const int*)  d_in[0];
    const int*   questions = (const int*)  d_in[1];
    const float* emb       = (const float*)d_in[2];
    const float* Wih_f = (const float*)d_in[3];
    const float* Whh_f = (const float*)d_in[4];
    const float* bih_f = (const float*)d_in[5];
    const float* bhh_f = (const float*)d_in[6];
    const float* Wih_b = (const float*)d_in[7];
    const float* Whh_b = (const float*)d_in[8];
    const float* bih_b = (const float*)d_in[9];
    const float* bhh_b = (const float*)d_in[10];
    const float* Wih_q = (const float*)d_in[11];
    const float* Whh_q = (const float*)d_in[12];
    const float* bih_q = (const float*)d_in[13];
    const float* bhh_q = (const float*)d_in[14];
    const float* Wo    = (const float*)d_in[15];
    const float* bo    = (const float*)d_in[16];
    float* out = (float*)d_out;

    // resolve device-global scratch addresses for the generic GEMM
    void *p_ctx, *p_qemb, *p_gif, *p_gib, *p_giq, *p_v;
    cudaGetSymbolAddress(&p_ctx,  g_ctx);
    cudaGetSymbolAddress(&p_qemb, g_qemb);
    cudaGetSymbolAddress(&p_gif,  g_gif);
    cudaGetSymbolAddress(&p_gib,  g_gib);
    cudaGetSymbolAddress(&p_giq,  g_giq);
    cudaGetSymbolAddress(&p_v,    g_v);

    init_h<<<(3*2*Bz*Hz + 255)/256, 256>>>();
    transpose_whh<<<dim3(H3/32, Hz/32, 3), dim3(32, 8)>>>(Whh_f, Whh_b, Whh_q);
    embed_ctx<<<Bz*Sz, Hz>>>(contexts, emb);
    embed_q  <<<Bz*TQz, Hz>>>(questions, emb);

    // gi GEMMs (bias = bih folded in)
    gemm_nt<<<dim3(H3/128, (Bz*Sz)/128),  256>>>((const float*)p_ctx,  Wih_f, bih_f, (float*)p_gif, Bz*Sz,  H3, Hz);
    gemm_nt<<<dim3(H3/128, (Bz*Sz)/128),  256>>>((const float*)p_ctx,  Wih_b, bih_b, (float*)p_gib, Bz*Sz,  H3, Hz);
    gemm_nt<<<dim3(H3/128, (Bz*TQz)/128), 256>>>((const float*)p_qemb, Wih_q, bih_q, (float*)p_giq, Bz*TQz, H3, Hz);

    // recurrence: fwd + bwd (50 steps) and question (first 32 steps), fused per step
    for (int t = 0; t < Sz; t++)
        gru_step<<<dim3(Bz/32, Hz/16, 3), 128>>>(t, t & 1, bhh_f, bhh_b, bhh_q);

    attn_kernel<<<Bz, Hz>>>();

    // out = tanh(q*read) @ Wo^T + bo : (128, 50257)
    gemm_nt<<<dim3((Vz + 127)/128, 1), 256>>>((const float*)p_v, Wo, bo, out, Bz, Vz, Hz);
}